// round 15
// baseline (speedup 1.0000x reference)
#include <cuda_runtime.h>
#include <cstdint>

#define SDIM 2048
#define EDIM 256
#define BDIM 8

__device__ float g_Q[BDIM * SDIM * EDIM];      // Q[b][s][f]
__device__ float g_poolT[BDIM * SDIM * EDIM];  // pooled^T [b][s][e], tf32-rounded
__device__ float g_Wqr[EDIM * EDIM];           // Wq tf32-rounded
__device__ float g_Wor[EDIM * EDIM];           // Wo tf32-rounded

static __device__ __forceinline__ uint32_t smem_u32(const void* p) {
    uint32_t a;
    asm("{ .reg .u64 t; cvta.to.shared.u64 t, %1; cvt.u32.u64 %0, t; }" : "=r"(a) : "l"(p));
    return a;
}
static __device__ __forceinline__ void cp4(uint32_t dst, const float* src) {
    asm volatile("cp.async.ca.shared.global [%0], [%1], 4;" :: "r"(dst), "l"(src));
}
static __device__ __forceinline__ void cp16(uint32_t dst, const float* src) {
    asm volatile("cp.async.ca.shared.global [%0], [%1], 16;" :: "r"(dst), "l"(src));
}
static __device__ __forceinline__ void cp_commit() {
    asm volatile("cp.async.commit_group;" ::: "memory");
}
template <int N>
static __device__ __forceinline__ void cp_wait() {
    asm volatile("cp.async.wait_group %0;" :: "n"(N) : "memory");
}
static __device__ __forceinline__ uint32_t rntf32(float f) {
    uint32_t u;
    asm("cvt.rn.tf32.f32 %0, %1;" : "=r"(u) : "f"(f));
    return u;
}

// mma.sync m16n8k8 tf32: D += A*B  (row.col), fp32 accum
static __device__ __forceinline__ void mma_tf32(float* d, const uint32_t* a, const uint32_t* b) {
    asm volatile(
        "mma.sync.aligned.m16n8k8.row.col.f32.tf32.tf32.f32 "
        "{%0,%1,%2,%3}, {%4,%5,%6,%7}, {%8,%9}, {%0,%1,%2,%3};"
        : "+f"(d[0]), "+f"(d[1]), "+f"(d[2]), "+f"(d[3])
        : "r"(a[0]), "r"(a[1]), "r"(a[2]), "r"(a[3]), "r"(b[0]), "r"(b[1]));
}

#define LDSM_X4(r, a)                                                     \
    asm volatile("ldmatrix.sync.aligned.m8n8.x4.shared.b16 "              \
                 "{%0,%1,%2,%3}, [%4];"                                   \
                 : "=r"((r)[0]), "=r"((r)[1]), "=r"((r)[2]), "=r"((r)[3]) \
                 : "r"(a))

// ---------------------------------------------------------------------------
// tf32 tensor-core GEMM — R8 configuration VERBATIM (empirical best).
// ---------------------------------------------------------------------------
template <int TRANS_A, int CVT_A, int BIAS_M>
__global__ void __launch_bounds__(256, 2)
gemm_mma(const float* __restrict__ A, int lda, long sA,
         const float* __restrict__ B, int ldb, long sB,
         float* __restrict__ C, int ldc, long sC,
         const float* __restrict__ bias, float scale) {
    extern __shared__ float smraw[];
    const uint32_t smb128 = (smem_u32(smraw) + 127) & ~127u;

    const int tid = threadIdx.x, lane = tid & 31, wid = tid >> 5;
    const int wm = wid & 3, wn = wid >> 2;
    const int bn0 = blockIdx.x * 128, bm0 = blockIdx.y * 128;
    A += sA * blockIdx.z; B += sB * blockIdx.z; C += sC * blockIdx.z;

    float d[2][8][4];
#pragma unroll
    for (int mt = 0; mt < 2; mt++)
#pragma unroll
        for (int nt = 0; nt < 8; nt++)
#pragma unroll
            for (int q = 0; q < 4; q++) d[mt][nt][q] = 0.0f;

    const int r7 = lane & 7;
    uint32_t offAb[2], offBb[4];
#pragma unroll
    for (int mt = 0; mt < 2; mt++) {
        int m = wm * 32 + mt * 16 + r7 + ((lane >> 3) & 1) * 8;
        offAb[mt] = (uint32_t)(m * 128 + (((lane >> 4) ^ r7) << 4));
    }
#pragma unroll
    for (int p = 0; p < 4; p++) {
        int n = wn * 64 + p * 16 + r7 + ((lane >> 4) & 1) * 8;
        offBb[p] = (uint32_t)(n * 128 + ((((lane >> 3) & 1) ^ r7) << 4));
    }

    auto fill = [&](int slot, int k0) {
        uint32_t aS = smb128 + slot * 32768;
        uint32_t bS = aS + 16384;
        if (TRANS_A) {
#pragma unroll
            for (int p = 0; p < 16; p++) {
                int idx = tid + p * 256;
                int m = idx & 127, kk = idx >> 7;
                cp4(aS + m * 128 + ((((kk >> 2) ^ (m & 7)) << 4)) + (kk & 3) * 4,
                    A + (long)(k0 + kk) * lda + bm0 + m);
            }
        } else {
#pragma unroll
            for (int p = 0; p < 4; p++) {
                int idx = tid + p * 256;
                int row = idx >> 3, ch = idx & 7;
                cp16(aS + row * 128 + (((ch ^ (row & 7)) << 4)),
                     A + (long)(bm0 + row) * lda + k0 + ch * 4);
            }
        }
#pragma unroll
        for (int p = 0; p < 4; p++) {
            int idx = tid + p * 256;
            int row = idx >> 3, ch = idx & 7;
            cp16(bS + row * 128 + (((ch ^ (row & 7)) << 4)),
                 B + (long)(bn0 + row) * ldb + k0 + ch * 4);
        }
    };

    auto compute = [&](int slot) {
        uint32_t aS = smb128 + slot * 32768;
        uint32_t bS = aS + 16384;
#pragma unroll
        for (int k8 = 0; k8 < 4; k8++) {
            const uint32_t kx = (uint32_t)(k8 << 5);
            uint32_t afr[2][4], bfr[4][4];
#pragma unroll
            for (int mt = 0; mt < 2; mt++) {
                LDSM_X4(afr[mt], (aS + offAb[mt]) ^ kx);
                if (CVT_A) {
#pragma unroll
                    for (int q = 0; q < 4; q++)
                        afr[mt][q] = rntf32(__uint_as_float(afr[mt][q]));
                }
            }
#pragma unroll
            for (int p = 0; p < 4; p++) LDSM_X4(bfr[p], (bS + offBb[p]) ^ kx);
#pragma unroll
            for (int mt = 0; mt < 2; mt++)
#pragma unroll
                for (int p = 0; p < 4; p++) {
                    mma_tf32(d[mt][2 * p],     afr[mt], &bfr[p][0]);
                    mma_tf32(d[mt][2 * p + 1], afr[mt], &bfr[p][2]);
                }
        }
    };

    fill(0, 0); cp_commit();
    fill(1, 32); cp_commit();

#pragma unroll 1
    for (int kt = 0; kt < 8; kt++) {
        if (kt == 7) cp_wait<0>(); else cp_wait<1>();
        __syncthreads();
        if (kt + 2 < 8) { fill((kt + 2) % 3, (kt + 2) * 32); cp_commit(); }
        compute(kt % 3);
    }

    const int mrow = bm0 + wm * 32 + (lane >> 2);
    const int ncol = bn0 + wn * 64 + (lane & 3) * 2;
#pragma unroll
    for (int mt = 0; mt < 2; mt++) {
        int m0 = mrow + mt * 16;
#pragma unroll
        for (int nt = 0; nt < 8; nt++) {
            int c = ncol + nt * 8;
            float b0, b1, b2;
            if (BIAS_M) { b0 = bias[m0]; b2 = bias[m0 + 8]; b1 = 0.0f; }
            else { b0 = bias[c]; b1 = bias[c + 1]; b2 = 0.0f; }
            float2 lo, hi;
            if (BIAS_M) {
                lo.x = (d[mt][nt][0] + b0) * scale; lo.y = (d[mt][nt][1] + b0) * scale;
                hi.x = (d[mt][nt][2] + b2) * scale; hi.y = (d[mt][nt][3] + b2) * scale;
            } else {
                lo.x = (d[mt][nt][0] + b0) * scale; lo.y = (d[mt][nt][1] + b1) * scale;
                hi.x = (d[mt][nt][2] + b0) * scale; hi.y = (d[mt][nt][3] + b1) * scale;
            }
            *(float2*)(C + (long)m0 * ldc + c) = lo;
            *(float2*)(C + (long)(m0 + 8) * ldc + c) = hi;
        }
    }
}

// ---------------------------------------------------------------------------
__global__ void round_weights(const float* __restrict__ Wq, const float* __restrict__ Wo) {
    int i = blockIdx.x * 256 + threadIdx.x;
    const float4 v = ((const float4*)(blockIdx.y ? Wo : Wq))[i];
    float4 r;
    r.x = __uint_as_float(rntf32(v.x));
    r.y = __uint_as_float(rntf32(v.y));
    r.z = __uint_as_float(rntf32(v.z));
    r.w = __uint_as_float(rntf32(v.w));
    ((float4*)(blockIdx.y ? g_Wor : g_Wqr))[i] = r;
}

// ---------------------------------------------------------------------------
// Fused attention + pooling v2. SBLK=32, NO smem aliasing:
//  - Q tile (cp16 group A) and x tile (cp4 group B) issued together up front;
//    dot phase waits only on Q, so the x load is fully hidden under P2a.
//  - XS stride 41 (odd): conflict-free P4 reads; coalesced global loads.
//  - 84KB smem -> 2 CTAs/SM; grid 512 -> cross-CTA phase overlap.
// ---------------------------------------------------------------------------
__global__ void __launch_bounds__(256, 2)
attnpool_fused(const float* __restrict__ x, const float* __restrict__ bq) {
    extern __shared__ float sf[];
    float* QS = sf;                    // 40 rows x 256 = 10240 floats
    float* XS = sf + 10240;            // 256 e x 41    = 10496
    float* d_sm = sf + 10240 + 10496;  // 40 x 8        = 320
    float* a_sm = d_sm + 320;          // 32 x 12       = 384

    const int b = blockIdx.y, s0 = blockIdx.x * 32;
    const int tid = threadIdx.x, lane = tid & 31, w = tid >> 5;
    const float* Qb = g_Q + (long)b * SDIM * EDIM;
    const uint32_t qsA = smem_u32(QS), xsA = smem_u32(XS);
    const bool interior = (blockIdx.x > 0) && (blockIdx.x + 1 < gridDim.x);

    // ---- P1a: Q tile rows 0..39 (s = s0-4+r), cp16, group A ----
#pragma unroll
    for (int p = 0; p < 10; p++) {
        int idx = tid + p * 256;
        int r = idx >> 6, f4 = idx & 63;
        int s = s0 - 4 + r;
        if (interior || (unsigned)s < SDIM) {
            cp16(qsA + idx * 16, Qb + (long)s * EDIM + f4 * 4);
        } else {
            *(float4*)&QS[idx * 4] = ((const float4*)bq)[f4];
        }
    }
    cp_commit();  // group A (Q)

    // ---- P1b: x tile XS[e][i], i=0..39 (s = s0-4+i), cp4, group B ----
    {
        const float* xb = x + (long)b * EDIM * SDIM;
#pragma unroll 1
        for (int p = 0; p < 32; p++) {
            int e = p * 8 + w;
            const float* xe = xb + (long)e * SDIM;
            int g = s0 - 4 + lane;
            if (interior || (unsigned)g < SDIM) cp4(xsA + (e * 41 + lane) * 4, xe + g);
            else XS[e * 41 + lane] = 0.0f;
            if (lane < 8) {
                int i2 = 32 + lane, g2 = s0 - 4 + i2;
                if (interior || (unsigned)g2 < SDIM) cp4(xsA + (e * 41 + i2) * 4, xe + g2);
                else XS[e * 41 + i2] = 0.0f;
            }
        }
    }
    cp_commit();  // group B (x)

    cp_wait<1>();  // Q ready; x still in flight
    __syncthreads();

    // ---- P2a: symmetric dots D[t][j] = QS[t].QS[t+j], t=0..39, j=0..4 ----
    {
        int t0 = w * 5;  // 8 warps x 5 rows = 40
        float R[5][8];
#pragma unroll
        for (int q = 0; q < 4; q++) {
            int rr = min(t0 + q, 39);
            *(float4*)&R[q][0] = ((float4*)QS)[rr * 64 + lane * 2];
            *(float4*)&R[q][4] = ((float4*)QS)[rr * 64 + lane * 2 + 1];
        }
#pragma unroll 1
        for (int i = 0; i < 5; i++) {
            int t = t0 + i;
            int s4 = (i + 4) % 5;
            if (t + 4 < 40) {
                *(float4*)&R[s4][0] = ((float4*)QS)[(t + 4) * 64 + lane * 2];
                *(float4*)&R[s4][4] = ((float4*)QS)[(t + 4) * 64 + lane * 2 + 1];
            }
            float keep = 0.0f;
#pragma unroll
            for (int j = 0; j < 5; j++) {
                if (t + j < 40) {
                    float p = 0.0f;
#pragma unroll
                    for (int f = 0; f < 8; f++) p += R[i % 5][f] * R[(i + j) % 5][f];
#pragma unroll
                    for (int off = 16; off; off >>= 1) p += __shfl_xor_sync(0xffffffffu, p, off);
                    if (lane == j) keep = p;
                }
            }
            if (lane < 5) d_sm[t * 8 + lane] = keep;
        }
    }
    __syncthreads();

    // ---- P2b: softmax (threads 0..31) ----
    if (tid < 32) {
        const int ls = tid;
        const float inv_scale = 1.0f / 24.0f;
        float E[9];
        E[4] = d_sm[(ls + 4) * 8];
#pragma unroll
        for (int j = 1; j <= 4; j++) {
            E[4 + j] = d_sm[(ls + 4) * 8 + j];
            E[4 - j] = d_sm[(ls + 4 - j) * 8 + j];
        }
        float mx = -1e30f;
#pragma unroll
        for (int l = 0; l < 9; l++) { E[l] *= inv_scale; mx = fmaxf(mx, E[l]); }
        float sum = 0.0f;
        float ev[9];
#pragma unroll
        for (int l = 0; l < 9; l++) { ev[l] = __expf(E[l] - mx); sum += ev[l]; }
        float inv = 1.0f / sum;
#pragma unroll
        for (int l = 0; l < 9; l++) a_sm[ls * 12 + l] = ev[l] * inv;
    }

    cp_wait<0>();  // x ready
    __syncthreads();

    // ---- P4: pooling. thread <-> e (coalesced STG), 4 chunks of 8 s ----
    {
        const int e = tid;
        const float* Xe = XS + e * 41;
        float* outb = g_poolT + ((long)b * SDIM + s0) * EDIM + e;
#pragma unroll 1
        for (int sc = 0; sc < 4; sc++) {
            const int sb = sc * 8;
            float xw[16];
#pragma unroll
            for (int i = 0; i < 16; i++) xw[i] = Xe[sb + i];
#pragma unroll
            for (int si = 0; si < 8; si++) {
                int s = sb + si;
                float4 a03 = *(const float4*)&a_sm[s * 12];
                float4 a47 = *(const float4*)&a_sm[s * 12 + 4];
                float a8 = a_sm[s * 12 + 8];
                float acc = a03.x * xw[si]     + a03.y * xw[si + 1] +
                            a03.z * xw[si + 2] + a03.w * xw[si + 3] +
                            a47.x * xw[si + 4] + a47.y * xw[si + 5] +
                            a47.z * xw[si + 6] + a47.w * xw[si + 7] +
                            a8    * xw[si + 8];
                outb[(long)s * EDIM] = __uint_as_float(rntf32(acc));
            }
        }
    }
}

// ---------------------------------------------------------------------------
extern "C" void kernel_launch(void* const* d_in, const int* in_sizes, int n_in,
                              void* d_out, int out_size) {
    const float* x  = (const float*)d_in[0];
    const float* Wq = (const float*)d_in[1];
    const float* bq = (const float*)d_in[2];
    const float* Wo = (const float*)d_in[3];
    const float* bo = (const float*)d_in[4];
    float* out = (float*)d_out;

    float *Qp, *pt, *wqr, *wor;
    cudaGetSymbolAddress((void**)&Qp, g_Q);
    cudaGetSymbolAddress((void**)&pt, g_poolT);
    cudaGetSymbolAddress((void**)&wqr, g_Wqr);
    cudaGetSymbolAddress((void**)&wor, g_Wor);

    const int SMEM_G = 3 * 32768 + 128;
    const int SMEM_F = (10240 + 10496 + 320 + 384) * 4;  // 85760 B -> 2 CTAs/SM
    cudaFuncSetAttribute((const void*)gemm_mma<1, 1, 0>, cudaFuncAttributeMaxDynamicSharedMemorySize, SMEM_G);
    cudaFuncSetAttribute((const void*)gemm_mma<0, 0, 1>, cudaFuncAttributeMaxDynamicSharedMemorySize, SMEM_G);
    cudaFuncSetAttribute((const void*)attnpool_fused, cudaFuncAttributeMaxDynamicSharedMemorySize, SMEM_F);

    // 0) round weights to tf32 grid
    round_weights<<<dim3(64, 2), 256>>>(Wq, Wo);

    // 1) Q[b][s][f] = sum_e x[b][e][s]*Wqr[f][e] + bq[f]   (m=s, n=f, k=e)
    gemm_mma<1, 1, 0><<<dim3(2, 16, BDIM), 256, SMEM_G>>>(
        x, SDIM, (long)EDIM * SDIM,
        wqr, EDIM, 0L,
        Qp, EDIM, (long)SDIM * EDIM,
        bq, 1.0f);

    // 1.5) dummy (idempotent) — aligns ncu so the 4th launch = fused kernel
    round_weights<<<dim3(64, 2), 256>>>(Wq, Wo);

    // 2) fused attention + pooling -> pooled^T[s][e] (tf32-rounded)
    attnpool_fused<<<dim3(SDIM / 32, BDIM), 256, SMEM_F>>>(x, bq);

    // 3) out[b][f][s] = (sum_e Wor[f][e]*pooled^T[s][e] + bo[f]) / 9   (m=f, n=s, k=e)
    gemm_mma<0, 0, 1><<<dim3(16, 2, BDIM), 256, SMEM_G>>>(
        wor, EDIM, 0L,
        pt, EDIM, (long)SDIM * EDIM,
        out, SDIM, (long)EDIM * SDIM,
        bo, 1.0f / 9.0f);
}

// round 16
// speedup vs baseline: 1.0813x; 1.0813x over previous
#include <cuda_runtime.h>
#include <cstdint>

#define SDIM 2048
#define EDIM 256
#define BDIM 8

__device__ float g_Q[BDIM * SDIM * EDIM];      // Q[b][s][f]
__device__ float g_Y[BDIM * SDIM * EDIM];      // Y[b][f][s] = Wo.x (no bias)
__device__ float g_attn[BDIM * SDIM * 16];     // 9 weights per (b,s), stride 16
__device__ float g_Wqr[EDIM * EDIM];           // Wq tf32-rounded
__device__ float g_Wor[EDIM * EDIM];           // Wo tf32-rounded

static __device__ __forceinline__ uint32_t smem_u32(const void* p) {
    uint32_t a;
    asm("{ .reg .u64 t; cvta.to.shared.u64 t, %1; cvt.u32.u64 %0, t; }" : "=r"(a) : "l"(p));
    return a;
}
static __device__ __forceinline__ void cp4(uint32_t dst, const float* src) {
    asm volatile("cp.async.ca.shared.global [%0], [%1], 4;" :: "r"(dst), "l"(src));
}
static __device__ __forceinline__ void cp16(uint32_t dst, const float* src) {
    asm volatile("cp.async.ca.shared.global [%0], [%1], 16;" :: "r"(dst), "l"(src));
}
static __device__ __forceinline__ void cp_commit() {
    asm volatile("cp.async.commit_group;" ::: "memory");
}
template <int N>
static __device__ __forceinline__ void cp_wait() {
    asm volatile("cp.async.wait_group %0;" :: "n"(N) : "memory");
}
static __device__ __forceinline__ uint32_t rntf32(float f) {
    uint32_t u;
    asm("cvt.rn.tf32.f32 %0, %1;" : "=r"(u) : "f"(f));
    return u;
}

// mma.sync m16n8k8 tf32: D += A*B  (row.col), fp32 accum
static __device__ __forceinline__ void mma_tf32(float* d, const uint32_t* a, const uint32_t* b) {
    asm volatile(
        "mma.sync.aligned.m16n8k8.row.col.f32.tf32.tf32.f32 "
        "{%0,%1,%2,%3}, {%4,%5,%6,%7}, {%8,%9}, {%0,%1,%2,%3};"
        : "+f"(d[0]), "+f"(d[1]), "+f"(d[2]), "+f"(d[3])
        : "r"(a[0]), "r"(a[1]), "r"(a[2]), "r"(a[3]), "r"(b[0]), "r"(b[1]));
}

#define LDSM_X4(r, a)                                                     \
    asm volatile("ldmatrix.sync.aligned.m8n8.x4.shared.b16 "              \
                 "{%0,%1,%2,%3}, [%4];"                                   \
                 : "=r"((r)[0]), "=r"((r)[1]), "=r"((r)[2]), "=r"((r)[3]) \
                 : "r"(a))

// ---------------------------------------------------------------------------
// tf32 tensor-core GEMM body — R8 pipeline (empirical best, ~85% of legacy
// tf32-HMMA ceiling). BM=BN=128, K=256 (8 chunks of 32), 8 warps (4m x 2n).
// TRANS_A/CVT_A: a[m][k] = A[k*lda+m], RN-rounded in registers (x operand).
// TRANS_B/CVT_B: b[n][k] = B[k*ldb+n], RN-rounded in registers (x operand).
// BIAS: 0 = none, 1 = by m, 2 = by n.
// ---------------------------------------------------------------------------
template <int TRANS_A, int CVT_A, int TRANS_B, int CVT_B, int BIAS>
static __device__ __forceinline__ void gemm_body(
    const float* __restrict__ A, int lda,
    const float* __restrict__ B, int ldb,
    float* __restrict__ C, int ldc,
    const float* __restrict__ bias, float scale,
    int bm0, int bn0, char* smraw) {
    const uint32_t smb128 = (smem_u32(smraw) + 127) & ~127u;
    const int tid = threadIdx.x, lane = tid & 31, wid = tid >> 5;
    const int wm = wid & 3, wn = wid >> 2;

    float d[2][8][4];
#pragma unroll
    for (int mt = 0; mt < 2; mt++)
#pragma unroll
        for (int nt = 0; nt < 8; nt++)
#pragma unroll
            for (int q = 0; q < 4; q++) d[mt][nt][q] = 0.0f;

    const int r7 = lane & 7;
    uint32_t offAb[2], offBb[4];
#pragma unroll
    for (int mt = 0; mt < 2; mt++) {
        int m = wm * 32 + mt * 16 + r7 + ((lane >> 3) & 1) * 8;
        offAb[mt] = (uint32_t)(m * 128 + (((lane >> 4) ^ r7) << 4));
    }
#pragma unroll
    for (int p = 0; p < 4; p++) {
        int n = wn * 64 + p * 16 + r7 + ((lane >> 4) & 1) * 8;
        offBb[p] = (uint32_t)(n * 128 + ((((lane >> 3) & 1) ^ r7) << 4));
    }

    auto fill = [&](int slot, int k0) {
        uint32_t aS = smb128 + slot * 32768;
        uint32_t bS = aS + 16384;
        if (TRANS_A) {
#pragma unroll
            for (int p = 0; p < 16; p++) {
                int idx = tid + p * 256;
                int m = idx & 127, kk = idx >> 7;
                cp4(aS + m * 128 + ((((kk >> 2) ^ (m & 7)) << 4)) + (kk & 3) * 4,
                    A + (long)(k0 + kk) * lda + bm0 + m);
            }
        } else {
#pragma unroll
            for (int p = 0; p < 4; p++) {
                int idx = tid + p * 256;
                int row = idx >> 3, ch = idx & 7;
                cp16(aS + row * 128 + (((ch ^ (row & 7)) << 4)),
                     A + (long)(bm0 + row) * lda + k0 + ch * 4);
            }
        }
        if (TRANS_B) {
#pragma unroll
            for (int p = 0; p < 16; p++) {
                int idx = tid + p * 256;
                int n = idx & 127, kk = idx >> 7;
                cp4(bS + n * 128 + ((((kk >> 2) ^ (n & 7)) << 4)) + (kk & 3) * 4,
                    B + (long)(k0 + kk) * ldb + bn0 + n);
            }
        } else {
#pragma unroll
            for (int p = 0; p < 4; p++) {
                int idx = tid + p * 256;
                int row = idx >> 3, ch = idx & 7;
                cp16(bS + row * 128 + (((ch ^ (row & 7)) << 4)),
                     B + (long)(bn0 + row) * ldb + k0 + ch * 4);
            }
        }
    };

    auto compute = [&](int slot) {
        uint32_t aS = smb128 + slot * 32768;
        uint32_t bS = aS + 16384;
#pragma unroll
        for (int k8 = 0; k8 < 4; k8++) {
            const uint32_t kx = (uint32_t)(k8 << 5);
            uint32_t afr[2][4], bfr[4][4];
#pragma unroll
            for (int mt = 0; mt < 2; mt++) {
                LDSM_X4(afr[mt], (aS + offAb[mt]) ^ kx);
                if (CVT_A) {
#pragma unroll
                    for (int q = 0; q < 4; q++)
                        afr[mt][q] = rntf32(__uint_as_float(afr[mt][q]));
                }
            }
#pragma unroll
            for (int p = 0; p < 4; p++) {
                LDSM_X4(bfr[p], (bS + offBb[p]) ^ kx);
                if (CVT_B) {
#pragma unroll
                    for (int q = 0; q < 4; q++)
                        bfr[p][q] = rntf32(__uint_as_float(bfr[p][q]));
                }
            }
#pragma unroll
            for (int mt = 0; mt < 2; mt++)
#pragma unroll
                for (int p = 0; p < 4; p++) {
                    mma_tf32(d[mt][2 * p],     afr[mt], &bfr[p][0]);
                    mma_tf32(d[mt][2 * p + 1], afr[mt], &bfr[p][2]);
                }
        }
    };

    fill(0, 0); cp_commit();
    fill(1, 32); cp_commit();

#pragma unroll 1
    for (int kt = 0; kt < 8; kt++) {
        if (kt == 7) cp_wait<0>(); else cp_wait<1>();
        __syncthreads();
        if (kt + 2 < 8) { fill((kt + 2) % 3, (kt + 2) * 32); cp_commit(); }
        compute(kt % 3);
    }

    const int mrow = bm0 + wm * 32 + (lane >> 2);
    const int ncol = bn0 + wn * 64 + (lane & 3) * 2;
#pragma unroll
    for (int mt = 0; mt < 2; mt++) {
        int m0 = mrow + mt * 16;
#pragma unroll
        for (int nt = 0; nt < 8; nt++) {
            int c = ncol + nt * 8;
            float b0 = 0.0f, b1 = 0.0f, b2 = 0.0f;
            if (BIAS == 1) { b0 = bias[m0]; b2 = bias[m0 + 8]; }
            else if (BIAS == 2) { b0 = bias[c]; b1 = bias[c + 1]; }
            float2 lo, hi;
            if (BIAS == 1) {
                lo.x = (d[mt][nt][0] + b0) * scale; lo.y = (d[mt][nt][1] + b0) * scale;
                hi.x = (d[mt][nt][2] + b2) * scale; hi.y = (d[mt][nt][3] + b2) * scale;
            } else if (BIAS == 2) {
                lo.x = (d[mt][nt][0] + b0) * scale; lo.y = (d[mt][nt][1] + b1) * scale;
                hi.x = (d[mt][nt][2] + b0) * scale; hi.y = (d[mt][nt][3] + b1) * scale;
            } else {
                lo.x = d[mt][nt][0] * scale; lo.y = d[mt][nt][1] * scale;
                hi.x = d[mt][nt][2] * scale; hi.y = d[mt][nt][3] * scale;
            }
            *(float2*)(C + (long)m0 * ldc + c) = lo;
            *(float2*)(C + (long)(m0 + 8) * ldc + c) = hi;
        }
    }
}

// ---------------------------------------------------------------------------
// Merged GEMM launch: z in [0,8) -> Q = x^T.Wqr + bq  (m=s, n=f)
//                     z in [8,16) -> Y = Wor.x        (m=f, n=s, no bias)
// ---------------------------------------------------------------------------
__global__ void __launch_bounds__(256, 2)
merged_gemm(const float* __restrict__ x, const float* __restrict__ bq,
            float* __restrict__ Qp, float* __restrict__ Yp,
            const float* __restrict__ wqr, const float* __restrict__ wor) {
    extern __shared__ char smraw[];
    const int z = blockIdx.z, t = blockIdx.x;
    if (z < BDIM) {
        gemm_body<1, 1, 0, 0, 2>(
            x + (long)z * EDIM * SDIM, SDIM,
            wqr, EDIM,
            Qp + (long)z * SDIM * EDIM, EDIM,
            bq, 1.0f, (t >> 1) * 128, (t & 1) * 128, smraw);
    } else {
        const int b = z - BDIM;
        gemm_body<0, 0, 1, 1, 0>(
            wor, EDIM,
            x + (long)b * EDIM * SDIM, SDIM,
            Yp + (long)b * EDIM * SDIM, SDIM,
            nullptr, 1.0f, (t & 1) * 128, (t >> 1) * 128, smraw);
    }
}

// ---------------------------------------------------------------------------
__global__ void round_weights(const float* __restrict__ Wq, const float* __restrict__ Wo) {
    int i = blockIdx.x * 256 + threadIdx.x;
    const float4 v = ((const float4*)(blockIdx.y ? Wo : Wq))[i];
    float4 r;
    r.x = __uint_as_float(rntf32(v.x));
    r.y = __uint_as_float(rntf32(v.y));
    r.z = __uint_as_float(rntf32(v.z));
    r.w = __uint_as_float(rntf32(v.w));
    ((float4*)(blockIdx.y ? g_Wor : g_Wqr))[i] = r;
}

// ---------------------------------------------------------------------------
// Attention weights (R8 version): softmax over 9-tap Q-dot window.
// ---------------------------------------------------------------------------
__global__ void __launch_bounds__(256) attn_kernel(const float* __restrict__ bq) {
    int b = blockIdx.y;
    int s0 = blockIdx.x * 32;
    __shared__ float Qs[40 * EDIM];

    const float* Qb = g_Q + (long)b * SDIM * EDIM;
    for (int idx = threadIdx.x; idx < 40 * 64; idx += 256) {
        int c = idx >> 6, v = idx & 63;
        int s = s0 - 4 + c;
        float4 val;
        if (s < 0 || s >= SDIM)
            val = ((const float4*)bq)[v];
        else
            val = ((const float4*)(Qb + (long)s * EDIM))[v];
        ((float4*)Qs)[c * 64 + v] = val;
    }
    __syncthreads();

    int w = threadIdx.x >> 5, lane = threadIdx.x & 31;
    const float inv_scale = 1.0f / 24.0f;
#pragma unroll
    for (int i = 0; i < 4; i++) {
        int ls = w * 4 + i;
        int cc = ls + 4;
        float4 c0 = ((float4*)Qs)[cc * 64 + lane];
        float4 c1 = ((float4*)Qs)[cc * 64 + 32 + lane];
        float myd = -1e30f;
#pragma unroll
        for (int l = 0; l < 9; l++) {
            int cl = cc + l - 4;
            float4 q0 = ((float4*)Qs)[cl * 64 + lane];
            float4 q1 = ((float4*)Qs)[cl * 64 + 32 + lane];
            float p = c0.x * q0.x + c0.y * q0.y + c0.z * q0.z + c0.w * q0.w +
                      c1.x * q1.x + c1.y * q1.y + c1.z * q1.z + c1.w * q1.w;
#pragma unroll
            for (int off = 16; off; off >>= 1) p += __shfl_xor_sync(0xffffffffu, p, off);
            if (lane == l) myd = p;
        }
        float eng = myd * inv_scale;
        float m = eng;
#pragma unroll
        for (int off = 16; off; off >>= 1) m = fmaxf(m, __shfl_xor_sync(0xffffffffu, m, off));
        float ev = (lane < 9) ? __expf(eng - m) : 0.0f;
        float sum = ev;
#pragma unroll
        for (int off = 16; off; off >>= 1) sum += __shfl_xor_sync(0xffffffffu, sum, off);
        float a = ev / sum;
        if (lane < 9) g_attn[(long)(b * SDIM + s0 + ls) * 16 + lane] = a;
    }
}

// ---------------------------------------------------------------------------
// Final pooling: out[b][f][s] = (sum_l a[b][s][l] * Y[b][f][s+l-4] + bo[f])/9
// Tile 32 f x 128 s; same layout in and out (no transpose); coalesced stores.
// ---------------------------------------------------------------------------
__global__ void __launch_bounds__(256) finalpool(const float* __restrict__ bo,
                                                 float* __restrict__ out) {
    int b = blockIdx.z;
    int f0 = blockIdx.y * 32;
    int s0 = blockIdx.x * 128;
    __shared__ float a_sm[128 * 13];
    __shared__ float y_sm[32 * 136];   // cols: s0-4 .. s0+131

    const int tid = threadIdx.x;

    if (tid < 128) {
        const float4* ga = (const float4*)(g_attn + ((long)(b * SDIM + s0 + tid) << 4));
        float4 a0 = ga[0], a1 = ga[1], a2 = ga[2];
        float* dst = &a_sm[tid * 13];
        dst[0] = a0.x; dst[1] = a0.y; dst[2] = a0.z; dst[3] = a0.w;
        dst[4] = a1.x; dst[5] = a1.y; dst[6] = a1.z; dst[7] = a1.w;
        dst[8] = a2.x;
    }

    const float* Yb = g_Y + ((long)b * EDIM + f0) * SDIM;
#pragma unroll
    for (int p = 0; p < 4; p++) {
        int idx = tid + p * 256;
        int f = idx >> 5, s4 = (idx & 31) << 2;
        float4 v = *(const float4*)(Yb + (long)f * SDIM + s0 + s4);
        *(float4*)&y_sm[f * 136 + 4 + s4] = v;
    }
    {
        int f = tid >> 3, h = tid & 7;
        int j = (h < 4) ? h : (128 + h);
        int s = s0 - 4 + j;
        y_sm[f * 136 + j] = (s >= 0 && s < SDIM) ? Yb[(long)f * SDIM + s] : 0.0f;
    }
    __syncthreads();

    int ts = tid & 31, te = tid >> 5;
    const float inv9 = 1.0f / 9.0f;
    float* outb = out + ((long)b * EDIM + f0) * SDIM + s0;
#pragma unroll
    for (int si = 0; si < 4; si++) {
        int ls = ts + si * 32;
        float a[9];
#pragma unroll
        for (int l = 0; l < 9; l++) a[l] = a_sm[ls * 13 + l];
#pragma unroll
        for (int j = 0; j < 4; j++) {
            int f = te * 4 + j;
            float acc = 0.0f;
#pragma unroll
            for (int l = 0; l < 9; l++) acc += a[l] * y_sm[f * 136 + ls + l];
            outb[(long)f * SDIM + ls] = (acc + bo[f0 + f]) * inv9;
        }
    }
}

// ---------------------------------------------------------------------------
extern "C" void kernel_launch(void* const* d_in, const int* in_sizes, int n_in,
                              void* d_out, int out_size) {
    const float* x  = (const float*)d_in[0];
    const float* Wq = (const float*)d_in[1];
    const float* bq = (const float*)d_in[2];
    const float* Wo = (const float*)d_in[3];
    const float* bo = (const float*)d_in[4];
    float* out = (float*)d_out;

    float *Qp, *Yp, *wqr, *wor;
    cudaGetSymbolAddress((void**)&Qp, g_Q);
    cudaGetSymbolAddress((void**)&Yp, g_Y);
    cudaGetSymbolAddress((void**)&wqr, g_Wqr);
    cudaGetSymbolAddress((void**)&wor, g_Wor);

    const int SMEM_G = 3 * 32768 + 128;
    cudaFuncSetAttribute((const void*)merged_gemm, cudaFuncAttributeMaxDynamicSharedMemorySize, SMEM_G);

    // 0) round weights (x2: second is idempotent, aligns ncu 4th launch = attn)
    round_weights<<<dim3(64, 2), 256>>>(Wq, Wo);
    round_weights<<<dim3(64, 2), 256>>>(Wq, Wo);

    // 1) merged GEMM: Q (z 0..7) and Y (z 8..15) in one launch
    merged_gemm<<<dim3(32, 1, 2 * BDIM), 256, SMEM_G>>>(x, bq, Qp, Yp, wqr, wor);

    // 2) attention weights (profiled launch)
    attn_kernel<<<dim3(SDIM / 32, BDIM), 256>>>(bq);

    // 3) final pooling: out = (attn * Y + bo) / 9
    finalpool<<<dim3(SDIM / 128, EDIM / 32, BDIM), 256>>>(bo, out);
}

// round 17
// speedup vs baseline: 1.2186x; 1.1270x over previous
#include <cuda_runtime.h>
#include <cstdint>

#define SDIM 2048
#define EDIM 256
#define BDIM 8

__device__ float g_Q[BDIM * SDIM * EDIM];      // Q[b][s][f]
__device__ float g_Y[BDIM * SDIM * EDIM];      // Y[b][f][s] = Wo.x (no bias)
__device__ float g_attn[BDIM * SDIM * 16];     // 9 weights per (b,s), stride 16
__device__ float g_Wqr[EDIM * EDIM];           // Wq tf32-rounded
__device__ float g_Wor[EDIM * EDIM];           // Wo tf32-rounded

static __device__ __forceinline__ uint32_t smem_u32(const void* p) {
    uint32_t a;
    asm("{ .reg .u64 t; cvta.to.shared.u64 t, %1; cvt.u32.u64 %0, t; }" : "=r"(a) : "l"(p));
    return a;
}
static __device__ __forceinline__ void cp4(uint32_t dst, const float* src) {
    asm volatile("cp.async.ca.shared.global [%0], [%1], 4;" :: "r"(dst), "l"(src));
}
static __device__ __forceinline__ void cp16(uint32_t dst, const float* src) {
    asm volatile("cp.async.ca.shared.global [%0], [%1], 16;" :: "r"(dst), "l"(src));
}
static __device__ __forceinline__ void cp_commit() {
    asm volatile("cp.async.commit_group;" ::: "memory");
}
template <int N>
static __device__ __forceinline__ void cp_wait() {
    asm volatile("cp.async.wait_group %0;" :: "n"(N) : "memory");
}
static __device__ __forceinline__ uint32_t rntf32(float f) {
    uint32_t u;
    asm("cvt.rn.tf32.f32 %0, %1;" : "=r"(u) : "f"(f));
    return u;
}

// mma.sync m16n8k8 tf32: D += A*B  (row.col), fp32 accum
static __device__ __forceinline__ void mma_tf32(float* d, const uint32_t* a, const uint32_t* b) {
    asm volatile(
        "mma.sync.aligned.m16n8k8.row.col.f32.tf32.tf32.f32 "
        "{%0,%1,%2,%3}, {%4,%5,%6,%7}, {%8,%9}, {%0,%1,%2,%3};"
        : "+f"(d[0]), "+f"(d[1]), "+f"(d[2]), "+f"(d[3])
        : "r"(a[0]), "r"(a[1]), "r"(a[2]), "r"(a[3]), "r"(b[0]), "r"(b[1]));
}

#define LDSM_X4(r, a)                                                     \
    asm volatile("ldmatrix.sync.aligned.m8n8.x4.shared.b16 "              \
                 "{%0,%1,%2,%3}, [%4];"                                   \
                 : "=r"((r)[0]), "=r"((r)[1]), "=r"((r)[2]), "=r"((r)[3]) \
                 : "r"(a))

// ---------------------------------------------------------------------------
// tf32 tensor-core GEMM body — R8 pipeline (≈85% of legacy tf32-HMMA ceiling).
// ---------------------------------------------------------------------------
template <int TRANS_A, int CVT_A, int TRANS_B, int CVT_B, int BIAS>
static __device__ __forceinline__ void gemm_body(
    const float* __restrict__ A, int lda,
    const float* __restrict__ B, int ldb,
    float* __restrict__ C, int ldc,
    const float* __restrict__ bias, float scale,
    int bm0, int bn0, char* smraw) {
    const uint32_t smb128 = (smem_u32(smraw) + 127) & ~127u;
    const int tid = threadIdx.x, lane = tid & 31, wid = tid >> 5;
    const int wm = wid & 3, wn = wid >> 2;

    float d[2][8][4];
#pragma unroll
    for (int mt = 0; mt < 2; mt++)
#pragma unroll
        for (int nt = 0; nt < 8; nt++)
#pragma unroll
            for (int q = 0; q < 4; q++) d[mt][nt][q] = 0.0f;

    const int r7 = lane & 7;
    uint32_t offAb[2], offBb[4];
#pragma unroll
    for (int mt = 0; mt < 2; mt++) {
        int m = wm * 32 + mt * 16 + r7 + ((lane >> 3) & 1) * 8;
        offAb[mt] = (uint32_t)(m * 128 + (((lane >> 4) ^ r7) << 4));
    }
#pragma unroll
    for (int p = 0; p < 4; p++) {
        int n = wn * 64 + p * 16 + r7 + ((lane >> 4) & 1) * 8;
        offBb[p] = (uint32_t)(n * 128 + ((((lane >> 3) & 1) ^ r7) << 4));
    }

    auto fill = [&](int slot, int k0) {
        uint32_t aS = smb128 + slot * 32768;
        uint32_t bS = aS + 16384;
        if (TRANS_A) {
#pragma unroll
            for (int p = 0; p < 16; p++) {
                int idx = tid + p * 256;
                int m = idx & 127, kk = idx >> 7;
                cp4(aS + m * 128 + ((((kk >> 2) ^ (m & 7)) << 4)) + (kk & 3) * 4,
                    A + (long)(k0 + kk) * lda + bm0 + m);
            }
        } else {
#pragma unroll
            for (int p = 0; p < 4; p++) {
                int idx = tid + p * 256;
                int row = idx >> 3, ch = idx & 7;
                cp16(aS + row * 128 + (((ch ^ (row & 7)) << 4)),
                     A + (long)(bm0 + row) * lda + k0 + ch * 4);
            }
        }
        if (TRANS_B) {
#pragma unroll
            for (int p = 0; p < 16; p++) {
                int idx = tid + p * 256;
                int n = idx & 127, kk = idx >> 7;
                cp4(bS + n * 128 + ((((kk >> 2) ^ (n & 7)) << 4)) + (kk & 3) * 4,
                    B + (long)(k0 + kk) * ldb + bn0 + n);
            }
        } else {
#pragma unroll
            for (int p = 0; p < 4; p++) {
                int idx = tid + p * 256;
                int row = idx >> 3, ch = idx & 7;
                cp16(bS + row * 128 + (((ch ^ (row & 7)) << 4)),
                     B + (long)(bn0 + row) * ldb + k0 + ch * 4);
            }
        }
    };

    auto compute = [&](int slot) {
        uint32_t aS = smb128 + slot * 32768;
        uint32_t bS = aS + 16384;
#pragma unroll
        for (int k8 = 0; k8 < 4; k8++) {
            const uint32_t kx = (uint32_t)(k8 << 5);
            uint32_t afr[2][4], bfr[4][4];
#pragma unroll
            for (int mt = 0; mt < 2; mt++) {
                LDSM_X4(afr[mt], (aS + offAb[mt]) ^ kx);
                if (CVT_A) {
#pragma unroll
                    for (int q = 0; q < 4; q++)
                        afr[mt][q] = rntf32(__uint_as_float(afr[mt][q]));
                }
            }
#pragma unroll
            for (int p = 0; p < 4; p++) {
                LDSM_X4(bfr[p], (bS + offBb[p]) ^ kx);
                if (CVT_B) {
#pragma unroll
                    for (int q = 0; q < 4; q++)
                        bfr[p][q] = rntf32(__uint_as_float(bfr[p][q]));
                }
            }
#pragma unroll
            for (int mt = 0; mt < 2; mt++)
#pragma unroll
                for (int p = 0; p < 4; p++) {
                    mma_tf32(d[mt][2 * p],     afr[mt], &bfr[p][0]);
                    mma_tf32(d[mt][2 * p + 1], afr[mt], &bfr[p][2]);
                }
        }
    };

    fill(0, 0); cp_commit();
    fill(1, 32); cp_commit();

#pragma unroll 1
    for (int kt = 0; kt < 8; kt++) {
        if (kt == 7) cp_wait<0>(); else cp_wait<1>();
        __syncthreads();
        if (kt + 2 < 8) { fill((kt + 2) % 3, (kt + 2) * 32); cp_commit(); }
        compute(kt % 3);
    }

    const int mrow = bm0 + wm * 32 + (lane >> 2);
    const int ncol = bn0 + wn * 64 + (lane & 3) * 2;
#pragma unroll
    for (int mt = 0; mt < 2; mt++) {
        int m0 = mrow + mt * 16;
#pragma unroll
        for (int nt = 0; nt < 8; nt++) {
            int c = ncol + nt * 8;
            float b0 = 0.0f, b1 = 0.0f, b2 = 0.0f;
            if (BIAS == 1) { b0 = bias[m0]; b2 = bias[m0 + 8]; }
            else if (BIAS == 2) { b0 = bias[c]; b1 = bias[c + 1]; }
            float2 lo, hi;
            if (BIAS == 1) {
                lo.x = (d[mt][nt][0] + b0) * scale; lo.y = (d[mt][nt][1] + b0) * scale;
                hi.x = (d[mt][nt][2] + b2) * scale; hi.y = (d[mt][nt][3] + b2) * scale;
            } else if (BIAS == 2) {
                lo.x = (d[mt][nt][0] + b0) * scale; lo.y = (d[mt][nt][1] + b1) * scale;
                hi.x = (d[mt][nt][2] + b0) * scale; hi.y = (d[mt][nt][3] + b1) * scale;
            } else {
                lo.x = d[mt][nt][0] * scale; lo.y = d[mt][nt][1] * scale;
                hi.x = d[mt][nt][2] * scale; hi.y = d[mt][nt][3] * scale;
            }
            *(float2*)(C + (long)m0 * ldc + c) = lo;
            *(float2*)(C + (long)(m0 + 8) * ldc + c) = hi;
        }
    }
}

// ---------------------------------------------------------------------------
// Merged GEMM launch: z in [0,8) -> Q = x^T.Wqr + bq; z in [8,16) -> Y = Wor.x
// ---------------------------------------------------------------------------
__global__ void __launch_bounds__(256, 2)
merged_gemm(const float* __restrict__ x, const float* __restrict__ bq,
            float* __restrict__ Qp, float* __restrict__ Yp,
            const float* __restrict__ wqr, const float* __restrict__ wor) {
    extern __shared__ char smraw[];
    const int z = blockIdx.z, t = blockIdx.x;
    if (z < BDIM) {
        gemm_body<1, 1, 0, 0, 2>(
            x + (long)z * EDIM * SDIM, SDIM,
            wqr, EDIM,
            Qp + (long)z * SDIM * EDIM, EDIM,
            bq, 1.0f, (t >> 1) * 128, (t & 1) * 128, smraw);
    } else {
        const int b = z - BDIM;
        gemm_body<0, 0, 1, 1, 0>(
            wor, EDIM,
            x + (long)b * EDIM * SDIM, SDIM,
            Yp + (long)b * EDIM * SDIM, SDIM,
            nullptr, 1.0f, (t & 1) * 128, (t >> 1) * 128, smraw);
    }
}

// ---------------------------------------------------------------------------
__global__ void round_weights(const float* __restrict__ Wq, const float* __restrict__ Wo) {
    int i = blockIdx.x * 256 + threadIdx.x;
    const float4 v = ((const float4*)(blockIdx.y ? Wo : Wq))[i];
    float4 r;
    r.x = __uint_as_float(rntf32(v.x));
    r.y = __uint_as_float(rntf32(v.y));
    r.z = __uint_as_float(rntf32(v.z));
    r.w = __uint_as_float(rntf32(v.w));
    ((float4*)(blockIdx.y ? g_Wor : g_Wqr))[i] = r;
}

// ---------------------------------------------------------------------------
// Attention weights v2: symmetric dots (D[t][j]=Q_t.Q_{t+j}, j=0..4) with
// INTERLEAVED shfl reduction trees (5 independent chains per level -> SHFL
// latency hidden by ILP). 8 warps x 5 rows; softmax assembles row s from
// D[s+4][j] and D[s+4-j][j] (R14-verified identity).
// ---------------------------------------------------------------------------
__global__ void __launch_bounds__(256) attn_kernel(const float* __restrict__ bq) {
    int b = blockIdx.y;
    int s0 = blockIdx.x * 32;
    __shared__ float Qs[40 * EDIM];
    __shared__ float d_sm[40 * 8];

    const float* Qb = g_Q + (long)b * SDIM * EDIM;
    for (int idx = threadIdx.x; idx < 40 * 64; idx += 256) {
        int c = idx >> 6, v = idx & 63;
        int s = s0 - 4 + c;
        float4 val;
        if (s < 0 || s >= SDIM)
            val = ((const float4*)bq)[v];
        else
            val = ((const float4*)(Qb + (long)s * EDIM))[v];
        ((float4*)Qs)[c * 64 + v] = val;
    }
    __syncthreads();

    const int w = threadIdx.x >> 5, lane = threadIdx.x & 31;
    const int t0 = w * 5;
    float R[5][8];
#pragma unroll
    for (int q = 0; q < 4; q++) {
        int rr = min(t0 + q, 39);
        *(float4*)&R[q][0] = ((float4*)Qs)[rr * 64 + lane * 2];
        *(float4*)&R[q][4] = ((float4*)Qs)[rr * 64 + lane * 2 + 1];
    }
#pragma unroll
    for (int i = 0; i < 5; i++) {
        int t = t0 + i;
        int s4 = (i + 4) % 5;
        if (t + 4 < 40) {
            *(float4*)&R[s4][0] = ((float4*)Qs)[(t + 4) * 64 + lane * 2];
            *(float4*)&R[s4][4] = ((float4*)Qs)[(t + 4) * 64 + lane * 2 + 1];
        }
        float p[5];
#pragma unroll
        for (int j = 0; j < 5; j++) {
            p[j] = 0.0f;
            if (t + j < 40) {
#pragma unroll
                for (int f = 0; f < 8; f++) p[j] += R[i % 5][f] * R[(i + j) % 5][f];
            }
        }
        // interleaved reduction: 5 independent chains per tree level
#pragma unroll
        for (int off = 16; off; off >>= 1) {
#pragma unroll
            for (int j = 0; j < 5; j++)
                p[j] += __shfl_xor_sync(0xffffffffu, p[j], off);
        }
        if (lane < 5) d_sm[t * 8 + lane] = p[lane];
    }
    __syncthreads();

    if (threadIdx.x < 32) {
        const int ls = threadIdx.x;
        const float inv_scale = 1.0f / 24.0f;
        float E[9];
        E[4] = d_sm[(ls + 4) * 8];
#pragma unroll
        for (int j = 1; j <= 4; j++) {
            E[4 + j] = d_sm[(ls + 4) * 8 + j];
            E[4 - j] = d_sm[(ls + 4 - j) * 8 + j];
        }
        float mx = -1e30f;
#pragma unroll
        for (int l = 0; l < 9; l++) { E[l] *= inv_scale; mx = fmaxf(mx, E[l]); }
        float sum = 0.0f;
        float ev[9];
#pragma unroll
        for (int l = 0; l < 9; l++) { ev[l] = __expf(E[l] - mx); sum += ev[l]; }
        float inv = 1.0f / sum;
#pragma unroll
        for (int l = 0; l < 9; l++) g_attn[(long)(b * SDIM + s0 + ls) * 16 + l] = ev[l] * inv;
    }
}

// ---------------------------------------------------------------------------
// Final pooling: out[b][f][s] = (sum_l a[b][s][l] * Y[b][f][s+l-4] + bo[f])/9
// ---------------------------------------------------------------------------
__global__ void __launch_bounds__(256) finalpool(const float* __restrict__ bo,
                                                 float* __restrict__ out) {
    int b = blockIdx.z;
    int f0 = blockIdx.y * 32;
    int s0 = blockIdx.x * 128;
    __shared__ float a_sm[128 * 13];
    __shared__ float y_sm[32 * 136];

    const int tid = threadIdx.x;

    if (tid < 128) {
        const float4* ga = (const float4*)(g_attn + ((long)(b * SDIM + s0 + tid) << 4));
        float4 a0 = ga[0], a1 = ga[1], a2 = ga[2];
        float* dst = &a_sm[tid * 13];
        dst[0] = a0.x; dst[1] = a0.y; dst[2] = a0.z; dst[3] = a0.w;
        dst[4] = a1.x; dst[5] = a1.y; dst[6] = a1.z; dst[7] = a1.w;
        dst[8] = a2.x;
    }

    const float* Yb = g_Y + ((long)b * EDIM + f0) * SDIM;
#pragma unroll
    for (int p = 0; p < 4; p++) {
        int idx = tid + p * 256;
        int f = idx >> 5, s4 = (idx & 31) << 2;
        float4 v = *(const float4*)(Yb + (long)f * SDIM + s0 + s4);
        *(float4*)&y_sm[f * 136 + 4 + s4] = v;
    }
    {
        int f = tid >> 3, h = tid & 7;
        int j = (h < 4) ? h : (128 + h);
        int s = s0 - 4 + j;
        y_sm[f * 136 + j] = (s >= 0 && s < SDIM) ? Yb[(long)f * SDIM + s] : 0.0f;
    }
    __syncthreads();

    int ts = tid & 31, te = tid >> 5;
    const float inv9 = 1.0f / 9.0f;
    float* outb = out + ((long)b * EDIM + f0) * SDIM + s0;
#pragma unroll
    for (int si = 0; si < 4; si++) {
        int ls = ts + si * 32;
        float a[9];
#pragma unroll
        for (int l = 0; l < 9; l++) a[l] = a_sm[ls * 13 + l];
#pragma unroll
        for (int j = 0; j < 4; j++) {
            int f = te * 4 + j;
            float acc = 0.0f;
#pragma unroll
            for (int l = 0; l < 9; l++) acc += a[l] * y_sm[f * 136 + ls + l];
            outb[(long)f * SDIM + ls] = (acc + bo[f0 + f]) * inv9;
        }
    }
}

// ---------------------------------------------------------------------------
extern "C" void kernel_launch(void* const* d_in, const int* in_sizes, int n_in,
                              void* d_out, int out_size) {
    const float* x  = (const float*)d_in[0];
    const float* Wq = (const float*)d_in[1];
    const float* bq = (const float*)d_in[2];
    const float* Wo = (const float*)d_in[3];
    const float* bo = (const float*)d_in[4];
    float* out = (float*)d_out;

    float *Qp, *Yp, *wqr, *wor;
    cudaGetSymbolAddress((void**)&Qp, g_Q);
    cudaGetSymbolAddress((void**)&Yp, g_Y);
    cudaGetSymbolAddress((void**)&wqr, g_Wqr);
    cudaGetSymbolAddress((void**)&wor, g_Wor);

    const int SMEM_G = 3 * 32768 + 128;
    cudaFuncSetAttribute((const void*)merged_gemm, cudaFuncAttributeMaxDynamicSharedMemorySize, SMEM_G);

    // 0) round weights to tf32 grid
    round_weights<<<dim3(64, 2), 256>>>(Wq, Wo);

    // 1) merged GEMM: Q (z 0..7) and Y (z 8..15) in one launch
    merged_gemm<<<dim3(32, 1, 2 * BDIM), 256, SMEM_G>>>(x, bq, Qp, Yp, wqr, wor);

    // 2) attention weights (symmetric + interleaved reduction)
    attn_kernel<<<dim3(SDIM / 32, BDIM), 256>>>(bq);

    // 3) final pooling: out = (attn * Y + bo) / 9  (profiled launch #4)
    finalpool<<<dim3(SDIM / 128, EDIM / 32, BDIM), 256>>>(bo, out);
}